// round 2
// baseline (speedup 1.0000x reference)
#include <cuda_runtime.h>
#include <cuda_bf16.h>
#include <math.h>

#define HIDN 256
#define NVAR 20
#define NHEAD 8
#define DHEAD 32
#define MTOK 16384          // B*T = 32*512
#define FFD 1024
#define ATT_SCALE 0.17677669529663687f   // 1/sqrt(32)
#define LN_EPS 1e-5f

// ---------------- scratch (device globals; no allocation allowed) ----------------
__device__ float g_S[NHEAD * HIDN];                 // [h][c] = wk[:,h-slice] @ q_h
__device__ float g_sbias[NHEAD];                    // q_h . bk_h
__device__ float g_cbias[HIDN];                     // bv @ wo + bo
__device__ float g_xw[(size_t)MTOK * 2048];         // [m][h*256+c] attn-weighted x per head
__device__ float g_ctx[(size_t)MTOK * HIDN];        // per-head ctx (bv excluded, folded into cbias)
__device__ float g_ao[(size_t)MTOK * HIDN];         // attn_out
__device__ float g_h1[(size_t)MTOK * HIDN];         // LN1 out
__device__ float g_h2[(size_t)MTOK * FFD];          // GELU(h1@w1+b1)
__device__ float g_h3[(size_t)MTOK * HIDN];         // h2@w2+b2
__device__ float g_proc[(size_t)MTOK * HIDN];       // LN2 out

// ---------------- K0: tiny precompute (1 block, 256 threads) ----------------
__global__ void k_pre(const float* __restrict__ cls, const float* __restrict__ wq,
                      const float* __restrict__ bq, const float* __restrict__ wk,
                      const float* __restrict__ bk, const float* __restrict__ wv,
                      const float* __restrict__ wo, const float* __restrict__ bo,
                      const float* __restrict__ bv) {
    __shared__ float q_s[HIDN];
    int t = threadIdx.x;
    // q = cls @ wq + bq
    float acc = bq[t];
    #pragma unroll 4
    for (int c = 0; c < HIDN; c++) acc += cls[c] * wq[c * HIDN + t];
    q_s[t] = acc;
    __syncthreads();
    // S[h][c] = sum_d wk[c][h*32+d] * q[h*32+d]
    for (int idx = t; idx < NHEAD * HIDN; idx += 256) {
        int h = idx >> 8, c = idx & 255;
        float s = 0.f;
        #pragma unroll 8
        for (int d = 0; d < DHEAD; d++) s += wk[c * HIDN + h * DHEAD + d] * q_s[h * DHEAD + d];
        g_S[idx] = s;
    }
    if (t < NHEAD) {
        float s = 0.f;
        #pragma unroll 8
        for (int d = 0; d < DHEAD; d++) s += bk[t * DHEAD + d] * q_s[t * DHEAD + d];
        g_sbias[t] = s;
    }
    // cbias[i] = sum_c bv[c]*wo[c][i] + bo[i]
    float cb = bo[t];
    #pragma unroll 4
    for (int c = 0; c < HIDN; c++) cb += bv[c] * wo[c * HIDN + t];
    g_cbias[t] = cb;
}

// ---------------- K1: fused attention (block per token, 256 threads) ----------------
// scores[h][v] = (x_v . S_h + sbias_h)*scale ; softmax over v per head ;
// xw[h][c] = sum_v attn[h][v] * x[v][c]
__global__ void k1_attn(const float* __restrict__ x) {
    __shared__ float x_s[NVAR * 257];
    __shared__ float S_s[NHEAD * 257];
    __shared__ float sc_s[NHEAD * NVAR];    // [h][v]
    __shared__ float attn_s[NVAR * NHEAD];  // [v][h]
    int m = blockIdx.x;
    int t = threadIdx.x;
    const float* xb = x + (size_t)m * (NVAR * HIDN);

    for (int i = t; i < NHEAD * HIDN; i += 256) S_s[(i >> 8) * 257 + (i & 255)] = g_S[i];
    for (int i = t; i < NVAR * HIDN; i += 256) x_s[(i / 256) * 257 + (i & 255)] = xb[i];
    __syncthreads();

    if (t < NHEAD * NVAR) {
        int h = t / NVAR, v = t % NVAR;
        const float* xr = &x_s[v * 257];
        const float* sr = &S_s[h * 257];
        float s = 0.f;
        #pragma unroll 8
        for (int c = 0; c < HIDN; c++) s += xr[c] * sr[c];
        sc_s[h * NVAR + v] = (s + g_sbias[h]) * ATT_SCALE;
    }
    __syncthreads();
    if (t < NHEAD) {
        float mx = -1e30f;
        #pragma unroll
        for (int v = 0; v < NVAR; v++) mx = fmaxf(mx, sc_s[t * NVAR + v]);
        float e[NVAR]; float sum = 0.f;
        #pragma unroll
        for (int v = 0; v < NVAR; v++) { e[v] = __expf(sc_s[t * NVAR + v] - mx); sum += e[v]; }
        float inv = 1.0f / sum;
        #pragma unroll
        for (int v = 0; v < NVAR; v++) attn_s[v * NHEAD + t] = e[v] * inv;
    }
    __syncthreads();

    // xw: thread t == channel; attn loads are warp-uniform -> LDS broadcast
    float acc[NHEAD] = {};
    #pragma unroll 4
    for (int v = 0; v < NVAR; v++) {
        float xv = x_s[v * 257 + t];
        #pragma unroll
        for (int j = 0; j < NHEAD; j++) acc[j] += attn_s[v * NHEAD + j] * xv;
    }
    float* xo = g_xw + (size_t)m * 2048;
    #pragma unroll
    for (int j = 0; j < NHEAD; j++) xo[j * 256 + t] = acc[j];
}

// ---------------- K2: per-head ctx GEMM ----------------
// ctx[m][h*32+j] = sum_c xw[m][h*256+c] * wv[c][h*32+j]
// grid (M/64, 8), block 128, tile 64x32, micro 4x4
__global__ void k2_ctx(const float* __restrict__ wv) {
    __shared__ float As[16][68];
    __shared__ float Bs[16][36];
    int t = threadIdx.x;
    int h = blockIdx.y;
    int row0 = blockIdx.x * 64;
    const float* A = g_xw + (size_t)row0 * 2048 + h * 256;   // row stride 2048
    const float* Bp = wv + h * DHEAD;                         // row stride 256
    int tx = t & 7, ty = t >> 3;
    float acc[4][4] = {};
    for (int kk = 0; kk < HIDN; kk += 16) {
        #pragma unroll
        for (int p = 0; p < 8; p++) {
            int k = t & 15, r = (t >> 4) + p * 8;
            As[k][r] = A[(size_t)r * 2048 + kk + k];
        }
        #pragma unroll
        for (int p = 0; p < 4; p++) {
            int j = t & 31, k = (t >> 5) + p * 4;
            Bs[k][j] = Bp[(size_t)(kk + k) * HIDN + j];
        }
        __syncthreads();
        #pragma unroll
        for (int k = 0; k < 16; k++) {
            float4 a = *(const float4*)&As[k][ty * 4];
            float4 b = *(const float4*)&Bs[k][tx * 4];
            acc[0][0] += a.x * b.x; acc[0][1] += a.x * b.y; acc[0][2] += a.x * b.z; acc[0][3] += a.x * b.w;
            acc[1][0] += a.y * b.x; acc[1][1] += a.y * b.y; acc[1][2] += a.y * b.z; acc[1][3] += a.y * b.w;
            acc[2][0] += a.z * b.x; acc[2][1] += a.z * b.y; acc[2][2] += a.z * b.z; acc[2][3] += a.z * b.w;
            acc[3][0] += a.w * b.x; acc[3][1] += a.w * b.y; acc[3][2] += a.w * b.z; acc[3][3] += a.w * b.w;
        }
        __syncthreads();
    }
    #pragma unroll
    for (int i = 0; i < 4; i++) {
        int row = row0 + ty * 4 + i;
        #pragma unroll
        for (int j = 0; j < 4; j++)
            g_ctx[(size_t)row * HIDN + h * DHEAD + tx * 4 + j] = acc[i][j];
    }
}

// ---------------- generic 64x64 tiled fp32 GEMM, block 256, micro 4x4 ----------------
// MODE 0: C = A@B + g_cbias[col]       (o-proj)
// MODE 1: C = gelu_exact(A@B + bias)   (FF1)
// MODE 2: C = A@B + bias               (FF2)
template <int MODE>
__global__ void k_gemm(const float* __restrict__ A, const float* __restrict__ B,
                       const float* __restrict__ bias, float* __restrict__ C,
                       int M, int K, int N) {
    __shared__ float As[16][68];
    __shared__ float Bs[16][68];
    int t = threadIdx.x;
    int row0 = blockIdx.y * 64;
    int col0 = blockIdx.x * 64;
    int tx = t & 15, ty = t >> 4;
    float acc[4][4] = {};
    for (int kk = 0; kk < K; kk += 16) {
        #pragma unroll
        for (int p = 0; p < 4; p++) {
            int idx = t + p * 256;
            int k = idx & 15, r = idx >> 4;
            As[k][r] = A[(size_t)(row0 + r) * K + kk + k];
        }
        #pragma unroll
        for (int p = 0; p < 4; p++) {
            int idx = t + p * 256;
            int j = idx & 63, k = idx >> 6;
            Bs[k][j] = B[(size_t)(kk + k) * N + col0 + j];
        }
        __syncthreads();
        #pragma unroll
        for (int k = 0; k < 16; k++) {
            float4 a = *(const float4*)&As[k][ty * 4];
            float4 b = *(const float4*)&Bs[k][tx * 4];
            acc[0][0] += a.x * b.x; acc[0][1] += a.x * b.y; acc[0][2] += a.x * b.z; acc[0][3] += a.x * b.w;
            acc[1][0] += a.y * b.x; acc[1][1] += a.y * b.y; acc[1][2] += a.y * b.z; acc[1][3] += a.y * b.w;
            acc[2][0] += a.z * b.x; acc[2][1] += a.z * b.y; acc[2][2] += a.z * b.z; acc[2][3] += a.z * b.w;
            acc[3][0] += a.w * b.x; acc[3][1] += a.w * b.y; acc[3][2] += a.w * b.z; acc[3][3] += a.w * b.w;
        }
        __syncthreads();
    }
    #pragma unroll
    for (int i = 0; i < 4; i++) {
        int row = row0 + ty * 4 + i;
        float4 o;
        float* op = (float*)&o;
        #pragma unroll
        for (int j = 0; j < 4; j++) {
            int col = col0 + tx * 4 + j;
            float v;
            if (MODE == 0)      v = acc[i][j] + g_cbias[col];
            else                v = acc[i][j] + bias[col];
            if (MODE == 1)      v = 0.5f * v * (1.0f + erff(v * 0.70710678118654752f));
            op[j] = v;
        }
        *(float4*)&C[(size_t)row * N + col0 + tx * 4] = o;
    }
}

// ---------------- LayerNorm: warp per token, 8 tokens per block ----------------
__global__ void k_ln(const float* __restrict__ in, const float* __restrict__ g,
                     const float* __restrict__ b, float* __restrict__ out) {
    int warp = threadIdx.x >> 5, lane = threadIdx.x & 31;
    int m = blockIdx.x * 8 + warp;
    const float* r = in + (size_t)m * HIDN;
    float v[8];
    float s = 0.f;
    #pragma unroll
    for (int i = 0; i < 8; i++) { v[i] = r[lane + 32 * i]; s += v[i]; }
    #pragma unroll
    for (int o = 16; o > 0; o >>= 1) s += __shfl_xor_sync(0xffffffffu, s, o);
    float mu = s * (1.0f / HIDN);
    float q = 0.f;
    #pragma unroll
    for (int i = 0; i < 8; i++) { float d = v[i] - mu; q += d * d; }
    #pragma unroll
    for (int o = 16; o > 0; o >>= 1) q += __shfl_xor_sync(0xffffffffu, q, o);
    float inv = rsqrtf(q * (1.0f / HIDN) + LN_EPS);
    #pragma unroll
    for (int i = 0; i < 8; i++) {
        int c = lane + 32 * i;
        out[(size_t)m * HIDN + c] = (v[i] - mu) * inv * g[c] + b[c];
    }
}

// ---------------- K_final: logits -> softmax -> vs_output + weights ----------------
// warp handles 2 tokens; block 256 = 16 tokens; grid 1024
__global__ void k_final(const float* __restrict__ x, const float* __restrict__ ww,
                        const float* __restrict__ bw, float* __restrict__ out) {
    __shared__ float ww_s[NVAR * 257];   // [j][c]
    __shared__ float bw_s[NVAR];
    int t = threadIdx.x;
    int warp = t >> 5, lane = t & 31;
    for (int idx = t; idx < HIDN * NVAR; idx += 256) {
        int c = idx / NVAR, j = idx % NVAR;
        ww_s[j * 257 + c] = ww[idx];
    }
    if (t < NVAR) bw_s[t] = bw[t];
    __syncthreads();

    const size_t WOFF = (size_t)MTOK * HIDN;
    #pragma unroll
    for (int tk = 0; tk < 2; tk++) {
        int m = blockIdx.x * 16 + warp * 2 + tk;
        const float* pr = g_proc + (size_t)m * HIDN;
        float lg[NVAR] = {};
        #pragma unroll
        for (int i = 0; i < 8; i++) {
            int c = lane + 32 * i;
            float p = pr[c];
            #pragma unroll
            for (int j = 0; j < NVAR; j++) lg[j] += p * ww_s[j * 257 + c];
        }
        #pragma unroll
        for (int j = 0; j < NVAR; j++) {
            #pragma unroll
            for (int o = 16; o > 0; o >>= 1) lg[j] += __shfl_xor_sync(0xffffffffu, lg[j], o);
            lg[j] += bw_s[j];
        }
        // softmax (replicated in every lane)
        float mx = -1e30f;
        #pragma unroll
        for (int j = 0; j < NVAR; j++) mx = fmaxf(mx, lg[j]);
        float sum = 0.f;
        #pragma unroll
        for (int j = 0; j < NVAR; j++) { lg[j] = __expf(lg[j] - mx); sum += lg[j]; }
        float inv = 1.0f / sum;
        #pragma unroll
        for (int j = 0; j < NVAR; j++) lg[j] *= inv;

        // weights output: lane j < 20 writes w[j]
        float myw = 0.f;
        #pragma unroll
        for (int j = 0; j < NVAR; j++) if (lane == j) myw = lg[j];
        if (lane < NVAR) out[WOFF + (size_t)m * NVAR + lane] = myw;

        // vs_output[c] = sum_v w[v] * x[m][v][c]
        const float* xb = x + (size_t)m * (NVAR * HIDN);
        #pragma unroll
        for (int i = 0; i < 8; i++) {
            int c = lane + 32 * i;
            float a = 0.f;
            #pragma unroll
            for (int v = 0; v < NVAR; v++) a += lg[v] * xb[v * HIDN + c];
            out[(size_t)m * HIDN + c] = a;
        }
    }
}

extern "C" void kernel_launch(void* const* d_in, const int* in_sizes, int n_in,
                              void* d_out, int out_size) {
    (void)in_sizes; (void)n_in; (void)out_size;
    const float* x     = (const float*)d_in[0];
    const float* cls   = (const float*)d_in[1];
    const float* wq    = (const float*)d_in[2];
    const float* bq    = (const float*)d_in[3];
    const float* wk    = (const float*)d_in[4];
    const float* bk    = (const float*)d_in[5];
    const float* wv    = (const float*)d_in[6];
    const float* bv    = (const float*)d_in[7];
    const float* wo    = (const float*)d_in[8];
    const float* bo    = (const float*)d_in[9];
    const float* ln1_g = (const float*)d_in[10];
    const float* ln1_b = (const float*)d_in[11];
    const float* w1    = (const float*)d_in[12];
    const float* b1    = (const float*)d_in[13];
    const float* w2    = (const float*)d_in[14];
    const float* b2    = (const float*)d_in[15];
    const float* ln2_g = (const float*)d_in[16];
    const float* ln2_b = (const float*)d_in[17];
    const float* ww    = (const float*)d_in[18];
    const float* bw    = (const float*)d_in[19];
    float* out = (float*)d_out;

    float *p_xw, *p_ctx, *p_ao, *p_h1, *p_h2, *p_h3, *p_proc;
    // device-symbol addresses via kernels only; use raw symbols inside kernels
    (void)p_xw; (void)p_ctx; (void)p_ao; (void)p_h1; (void)p_h2; (void)p_h3; (void)p_proc;

    k_pre<<<1, 256>>>(cls, wq, bq, wk, bk, wv, wo, bo, bv);
    k1_attn<<<MTOK, 256>>>(x);
    k2_ctx<<<dim3(MTOK / 64, NHEAD), 128>>>(wv);
    // o-proj: g_ao = g_ctx @ wo + cbias
    {
        float* A; float* C;
        cudaGetSymbolAddress((void**)&A, g_ctx);
        cudaGetSymbolAddress((void**)&C, g_ao);
        k_gemm<0><<<dim3(HIDN / 64, MTOK / 64), 256>>>(A, wo, nullptr, C, MTOK, HIDN, HIDN);
    }
    {
        float* A; float* C;
        cudaGetSymbolAddress((void**)&A, g_ao);
        cudaGetSymbolAddress((void**)&C, g_h1);
        k_ln<<<MTOK / 8, 256>>>(A, ln1_g, ln1_b, C);
    }
    {
        float* A; float* C;
        cudaGetSymbolAddress((void**)&A, g_h1);
        cudaGetSymbolAddress((void**)&C, g_h2);
        k_gemm<1><<<dim3(FFD / 64, MTOK / 64), 256>>>(A, w1, b1, C, MTOK, HIDN, FFD);
    }
    {
        float* A; float* C;
        cudaGetSymbolAddress((void**)&A, g_h2);
        cudaGetSymbolAddress((void**)&C, g_h3);
        k_gemm<2><<<dim3(HIDN / 64, MTOK / 64), 256>>>(A, w2, b2, C, MTOK, FFD, HIDN);
    }
    {
        float* A; float* C;
        cudaGetSymbolAddress((void**)&A, g_h3);
        cudaGetSymbolAddress((void**)&C, g_proc);
        k_ln<<<MTOK / 8, 256>>>(A, ln2_g, ln2_b, C);
    }
    k_final<<<MTOK / 16, 256>>>(x, ww, bw, out);
}

// round 4
// speedup vs baseline: 1.4403x; 1.4403x over previous
#include <cuda_runtime.h>
#include <cuda_bf16.h>
#include <math.h>
#include <cstdint>

#define HIDN 256
#define NVAR 20
#define NHEAD 8
#define DHEAD 32
#define MTOK 16384          // B*T
#define FFD 1024
#define ATT_SCALE 0.17677669529663687f
#define LN_EPS 1e-5f

// ======================= helpers =======================
__device__ __forceinline__ uint32_t smem_to_u32(const void* p) {
    uint32_t a;
    asm("{ .reg .u64 t; cvta.to.shared.u64 t, %1; cvt.u32.u64 %0, t; }" : "=r"(a) : "l"(p));
    return a;
}
__device__ __forceinline__ void ldm_x4(uint32_t& r0, uint32_t& r1, uint32_t& r2, uint32_t& r3,
                                       uint32_t addr) {
    asm volatile("ldmatrix.sync.aligned.m8n8.x4.shared.b16 {%0,%1,%2,%3}, [%4];"
                 : "=r"(r0), "=r"(r1), "=r"(r2), "=r"(r3) : "r"(addr));
}
__device__ __forceinline__ void mma_bf16(float* c, const uint32_t* a, const uint32_t* b) {
    asm volatile(
        "mma.sync.aligned.m16n8k16.row.col.f32.bf16.bf16.f32 "
        "{%0,%1,%2,%3}, {%4,%5,%6,%7}, {%8,%9}, {%0,%1,%2,%3};"
        : "+f"(c[0]), "+f"(c[1]), "+f"(c[2]), "+f"(c[3])
        : "r"(a[0]), "r"(a[1]), "r"(a[2]), "r"(a[3]), "r"(b[0]), "r"(b[1]));
}
__device__ __forceinline__ void split_bf16(float v, __nv_bfloat16& h, __nv_bfloat16& l) {
    h = __float2bfloat16(v);
    l = __float2bfloat16(v - __bfloat162float(h));
}
__device__ __forceinline__ float gelu_exact(float v) {
    return 0.5f * v * (1.0f + erff(v * 0.70710678118654752f));
}

// ======================= scratch =======================
__device__ __align__(256) float g_S[NHEAD * HIDN];
__device__ __align__(256) float g_sbias[NHEAD];
__device__ __align__(256) float g_cbias[HIDN];
__device__ __align__(256) __nv_bfloat16 g_xwh[(size_t)MTOK * 2048];
__device__ __align__(256) __nv_bfloat16 g_xwl[(size_t)MTOK * 2048];
__device__ __align__(256) __nv_bfloat16 g_ctxh[(size_t)MTOK * HIDN];
__device__ __align__(256) __nv_bfloat16 g_ctxl[(size_t)MTOK * HIDN];
__device__ __align__(256) float g_ao[(size_t)MTOK * HIDN];
__device__ __align__(256) __nv_bfloat16 g_h1h[(size_t)MTOK * HIDN];
__device__ __align__(256) __nv_bfloat16 g_h1l[(size_t)MTOK * HIDN];
__device__ __align__(256) __nv_bfloat16 g_h2h[(size_t)MTOK * FFD];
__device__ __align__(256) __nv_bfloat16 g_h2l[(size_t)MTOK * FFD];
__device__ __align__(256) float g_h3[(size_t)MTOK * HIDN];
__device__ __align__(256) float g_proc[(size_t)MTOK * HIDN];
// transposed + hi/lo-split weights: [N][K] bf16, K-major
__device__ __align__(256) __nv_bfloat16 g_woT_h[HIDN * HIDN], g_woT_l[HIDN * HIDN];
__device__ __align__(256) __nv_bfloat16 g_w1T_h[FFD * HIDN],  g_w1T_l[FFD * HIDN];
__device__ __align__(256) __nv_bfloat16 g_w2T_h[HIDN * FFD],  g_w2T_l[HIDN * FFD];
__device__ __align__(256) __nv_bfloat16 g_wvT_h[HIDN * HIDN], g_wvT_l[HIDN * HIDN];

// ======================= K0: tiny precompute =======================
__global__ void k_pre(const float* __restrict__ cls, const float* __restrict__ wq,
                      const float* __restrict__ bq, const float* __restrict__ wk,
                      const float* __restrict__ bk, const float* __restrict__ wo,
                      const float* __restrict__ bo, const float* __restrict__ bv) {
    __shared__ float q_s[HIDN];
    int t = threadIdx.x;
    float acc = bq[t];
    for (int c = 0; c < HIDN; c++) acc += cls[c] * wq[c * HIDN + t];
    q_s[t] = acc;
    __syncthreads();
    for (int idx = t; idx < NHEAD * HIDN; idx += 256) {
        int h = idx >> 8, c = idx & 255;
        float s = 0.f;
        #pragma unroll 8
        for (int d = 0; d < DHEAD; d++) s += wk[c * HIDN + h * DHEAD + d] * q_s[h * DHEAD + d];
        g_S[idx] = s;
    }
    if (t < NHEAD) {
        float s = 0.f;
        for (int d = 0; d < DHEAD; d++) s += bk[t * DHEAD + d] * q_s[t * DHEAD + d];
        g_sbias[t] = s;
    }
    float cb = bo[t];
    for (int c = 0; c < HIDN; c++) cb += bv[c] * wo[c * HIDN + t];
    g_cbias[t] = cb;
}

// ======================= transpose + split [K,N] -> [N][K] bf16 hi/lo ============
__global__ void k_wsplit(const float* __restrict__ w, __nv_bfloat16* __restrict__ hi,
                         __nv_bfloat16* __restrict__ lo, int K, int N) {
    int idx = blockIdx.x * 256 + threadIdx.x;
    if (idx >= K * N) return;
    int k = idx / N, n = idx % N;
    __nv_bfloat16 h, l;
    split_bf16(w[idx], h, l);
    hi[(size_t)n * K + k] = h;
    lo[(size_t)n * K + k] = l;
}

// ======================= K1: fused attention -> xw hi/lo =======================
__global__ void k1_attn(const float* __restrict__ x) {
    __shared__ float x_s[NVAR * 257];
    __shared__ float S_s[NHEAD * 257];
    __shared__ float sc_s[NHEAD * NVAR];
    __shared__ float attn_s[NVAR * NHEAD];
    int m = blockIdx.x;
    int t = threadIdx.x;
    const float* xb = x + (size_t)m * (NVAR * HIDN);

    for (int i = t; i < NHEAD * HIDN; i += 256) S_s[(i >> 8) * 257 + (i & 255)] = g_S[i];
    for (int i = t; i < NVAR * HIDN; i += 256) x_s[(i / 256) * 257 + (i & 255)] = xb[i];
    __syncthreads();

    if (t < NHEAD * NVAR) {
        int h = t / NVAR, v = t % NVAR;
        const float* xr = &x_s[v * 257];
        const float* sr = &S_s[h * 257];
        float s = 0.f;
        #pragma unroll 8
        for (int c = 0; c < HIDN; c++) s += xr[c] * sr[c];
        sc_s[h * NVAR + v] = (s + g_sbias[h]) * ATT_SCALE;
    }
    __syncthreads();
    if (t < NHEAD) {
        float mx = -1e30f;
        #pragma unroll
        for (int v = 0; v < NVAR; v++) mx = fmaxf(mx, sc_s[t * NVAR + v]);
        float e[NVAR]; float sum = 0.f;
        #pragma unroll
        for (int v = 0; v < NVAR; v++) { e[v] = __expf(sc_s[t * NVAR + v] - mx); sum += e[v]; }
        float inv = 1.0f / sum;
        #pragma unroll
        for (int v = 0; v < NVAR; v++) attn_s[v * NHEAD + t] = e[v] * inv;
    }
    __syncthreads();

    float acc[NHEAD] = {};
    #pragma unroll 4
    for (int v = 0; v < NVAR; v++) {
        float xv = x_s[v * 257 + t];
        #pragma unroll
        for (int j = 0; j < NHEAD; j++) acc[j] += attn_s[v * NHEAD + j] * xv;
    }
    size_t base = (size_t)m * 2048;
    #pragma unroll
    for (int j = 0; j < NHEAD; j++) {
        __nv_bfloat16 hh, ll;
        split_bf16(acc[j], hh, ll);
        g_xwh[base + j * 256 + t] = hh;
        g_xwl[base + j * 256 + t] = ll;
    }
}

// ======================= main split-bf16 MMA GEMM =======================
// C[M,N] = A[M,K] @ B[N,K]^T ; tile 128x128, KC=64, 8 warps (4m x 2n), warp tile 32x64
// MODE 0: fp32 out = acc + bias.  MODE 1: gelu(acc+bias) -> bf16 hi/lo.
#define KC 64
#define A_RS 144                    // smem row stride bytes (72 bf16)
#define MM_AH 0
#define MM_AL 18432
#define MM_BH 36864
#define MM_BL 55296
#define MM_TOTAL 73728

template <int MODE>
__global__ void __launch_bounds__(256) k_mma(
    const __nv_bfloat16* __restrict__ Ah, const __nv_bfloat16* __restrict__ Al,
    const __nv_bfloat16* __restrict__ Bh, const __nv_bfloat16* __restrict__ Bl,
    const float* __restrict__ bias, float* __restrict__ outF,
    __nv_bfloat16* __restrict__ outH, __nv_bfloat16* __restrict__ outL,
    int K, int N) {
    extern __shared__ __align__(16) char smem[];
    uint32_t sb = smem_to_u32(smem);
    int t = threadIdx.x, lane = t & 31, wid = t >> 5;
    int wm = wid & 3, wn = wid >> 2;
    int row0 = blockIdx.y * 128, col0 = blockIdx.x * 128;

    float acc[2][8][4] = {};

    for (int kk = 0; kk < K; kk += KC) {
        // ---- load 128x64 A(hi,lo) + 128x64 B(hi,lo) ----
        #pragma unroll
        for (int i = 0; i < 16; i++) {
            int idx = t + i * 256;
            int arr = idx >> 10;          // 0..3 = Ah,Al,Bh,Bl (constant per i)
            int rem = idx & 1023;
            int row = rem >> 3, seg = rem & 7;
            const __nv_bfloat16* src = (arr == 0) ? Ah : (arr == 1) ? Al : (arr == 2) ? Bh : Bl;
            size_t g = (size_t)(((arr < 2) ? row0 : col0) + row) * K + kk + seg * 8;
            *(uint4*)(smem + arr * 18432 + row * A_RS + seg * 16) = *(const uint4*)(src + g);
        }
        __syncthreads();

        #pragma unroll
        for (int ks = 0; ks < 4; ks++) {
            uint32_t a_h[2][4], a_l[2][4], b_h[8][2], b_l[8][2];
            #pragma unroll
            for (int mt = 0; mt < 2; mt++) {
                uint32_t off = (uint32_t)((wm * 32 + mt * 16 + (lane & 15)) * A_RS
                                          + (ks * 16 + ((lane >> 4) << 3)) * 2);
                ldm_x4(a_h[mt][0], a_h[mt][1], a_h[mt][2], a_h[mt][3], sb + MM_AH + off);
                ldm_x4(a_l[mt][0], a_l[mt][1], a_l[mt][2], a_l[mt][3], sb + MM_AL + off);
            }
            #pragma unroll
            for (int ng = 0; ng < 4; ng++) {
                uint32_t off = (uint32_t)((wn * 64 + ng * 16 + ((lane & 16) >> 1) + (lane & 7)) * A_RS
                                          + (ks * 16 + (lane & 8)) * 2);
                ldm_x4(b_h[2 * ng][0], b_h[2 * ng][1], b_h[2 * ng + 1][0], b_h[2 * ng + 1][1],
                       sb + MM_BH + off);
                ldm_x4(b_l[2 * ng][0], b_l[2 * ng][1], b_l[2 * ng + 1][0], b_l[2 * ng + 1][1],
                       sb + MM_BL + off);
            }
            #pragma unroll
            for (int mt = 0; mt < 2; mt++) {
                #pragma unroll
                for (int nt = 0; nt < 8; nt++) {
                    mma_bf16(acc[mt][nt], a_h[mt], b_h[nt]);
                    mma_bf16(acc[mt][nt], a_h[mt], b_l[nt]);
                    mma_bf16(acc[mt][nt], a_l[mt], b_h[nt]);
                }
            }
        }
        __syncthreads();
    }

    // ---- epilogue ----
    int g = lane >> 2, q = lane & 3;
    #pragma unroll
    for (int mt = 0; mt < 2; mt++) {
        int m0 = row0 + wm * 32 + mt * 16 + g;
        #pragma unroll
        for (int nt = 0; nt < 8; nt++) {
            int n = col0 + wn * 64 + nt * 8 + q * 2;
            float b0 = bias[n], b1 = bias[n + 1];
            float v00 = acc[mt][nt][0] + b0, v01 = acc[mt][nt][1] + b1;
            float v10 = acc[mt][nt][2] + b0, v11 = acc[mt][nt][3] + b1;
            if (MODE == 1) {
                v00 = gelu_exact(v00); v01 = gelu_exact(v01);
                v10 = gelu_exact(v10); v11 = gelu_exact(v11);
                __nv_bfloat16 h0, l0, h1, l1;
                split_bf16(v00, h0, l0); split_bf16(v01, h1, l1);
                *(__nv_bfloat162*)(outH + (size_t)m0 * N + n) = __nv_bfloat162(h0, h1);
                *(__nv_bfloat162*)(outL + (size_t)m0 * N + n) = __nv_bfloat162(l0, l1);
                split_bf16(v10, h0, l0); split_bf16(v11, h1, l1);
                *(__nv_bfloat162*)(outH + (size_t)(m0 + 8) * N + n) = __nv_bfloat162(h0, h1);
                *(__nv_bfloat162*)(outL + (size_t)(m0 + 8) * N + n) = __nv_bfloat162(l0, l1);
            } else {
                *(float2*)(outF + (size_t)m0 * N + n) = make_float2(v00, v01);
                *(float2*)(outF + (size_t)(m0 + 8) * N + n) = make_float2(v10, v11);
            }
        }
    }
}

// ======================= per-head ctx MMA GEMM =======================
// ctx[m][h*32+j] = sum_c xw[m][h*256+c] * wvT[h*32+j][c]
// grid (MTOK/128, 8), 256 thr, 8 warps each 16x32, KC=64, K=256
#define CT_AH 0
#define CT_AL 18432
#define CT_BH 36864
#define CT_BL 41472
__global__ void __launch_bounds__(256) k_mma_ctx() {
    __shared__ __align__(16) char smem[46080];
    uint32_t sb = smem_to_u32(smem);
    int t = threadIdx.x, lane = t & 31, wid = t >> 5;
    int row0 = blockIdx.x * 128, h = blockIdx.y;

    float acc[4][4] = {};

    for (int kk = 0; kk < HIDN; kk += KC) {
        #pragma unroll
        for (int i = 0; i < 8; i++) {       // A: 2048 uint4
            int idx = t + i * 256;
            int arr = idx >> 10;            // 0=hi,1=lo
            int rem = idx & 1023;
            int row = rem >> 3, seg = rem & 7;
            const __nv_bfloat16* src = arr ? g_xwl : g_xwh;
            size_t gidx = (size_t)(row0 + row) * 2048 + h * 256 + kk + seg * 8;
            *(uint4*)(smem + arr * 18432 + row * A_RS + seg * 16) = *(const uint4*)(src + gidx);
        }
        #pragma unroll
        for (int i = 0; i < 2; i++) {       // B: 512 uint4
            int idx = t + i * 256;
            int arr = idx >> 8;
            int rem = idx & 255;
            int row = rem >> 3, seg = rem & 7;
            const __nv_bfloat16* src = arr ? g_wvT_l : g_wvT_h;
            size_t gidx = (size_t)(h * 32 + row) * HIDN + kk + seg * 8;
            *(uint4*)(smem + CT_BH + arr * 4608 + row * A_RS + seg * 16) = *(const uint4*)(src + gidx);
        }
        __syncthreads();

        #pragma unroll
        for (int ks = 0; ks < 4; ks++) {
            uint32_t a_h[4], a_l[4], b_h[4][2], b_l[4][2];
            uint32_t aoff = (uint32_t)((wid * 16 + (lane & 15)) * A_RS
                                       + (ks * 16 + ((lane >> 4) << 3)) * 2);
            ldm_x4(a_h[0], a_h[1], a_h[2], a_h[3], sb + CT_AH + aoff);
            ldm_x4(a_l[0], a_l[1], a_l[2], a_l[3], sb + CT_AL + aoff);
            #pragma unroll
            for (int ng = 0; ng < 2; ng++) {
                uint32_t boff = (uint32_t)((ng * 16 + ((lane & 16) >> 1) + (lane & 7)) * A_RS
                                           + (ks * 16 + (lane & 8)) * 2);
                ldm_x4(b_h[2 * ng][0], b_h[2 * ng][1], b_h[2 * ng + 1][0], b_h[2 * ng + 1][1],
                       sb + CT_BH + boff);
                ldm_x4(b_l[2 * ng][0], b_l[2 * ng][1], b_l[2 * ng + 1][0], b_l[2 * ng + 1][1],
                       sb + CT_BL + boff);
            }
            #pragma unroll
            for (int nt = 0; nt < 4; nt++) {
                mma_bf16(acc[nt], a_h, b_h[nt]);
                mma_bf16(acc[nt], a_h, b_l[nt]);
                mma_bf16(acc[nt], a_l, b_h[nt]);
            }
        }
        __syncthreads();
    }

    int g = lane >> 2, q = lane & 3;
    int m0 = row0 + wid * 16 + g;
    #pragma unroll
    for (int nt = 0; nt < 4; nt++) {
        int n = h * 32 + nt * 8 + q * 2;
        __nv_bfloat16 h0, l0, h1, l1;
        split_bf16(acc[nt][0], h0, l0); split_bf16(acc[nt][1], h1, l1);
        *(__nv_bfloat162*)(g_ctxh + (size_t)m0 * HIDN + n) = __nv_bfloat162(h0, h1);
        *(__nv_bfloat162*)(g_ctxl + (size_t)m0 * HIDN + n) = __nv_bfloat162(l0, l1);
        split_bf16(acc[nt][2], h0, l0); split_bf16(acc[nt][3], h1, l1);
        *(__nv_bfloat162*)(g_ctxh + (size_t)(m0 + 8) * HIDN + n) = __nv_bfloat162(h0, h1);
        *(__nv_bfloat162*)(g_ctxl + (size_t)(m0 + 8) * HIDN + n) = __nv_bfloat162(l0, l1);
    }
}

// ======================= LayerNorm =======================
template <int OUTB>
__global__ void k_ln(const float* __restrict__ in, const float* __restrict__ g,
                     const float* __restrict__ b, float* __restrict__ outF,
                     __nv_bfloat16* __restrict__ oh, __nv_bfloat16* __restrict__ ol) {
    int warp = threadIdx.x >> 5, lane = threadIdx.x & 31;
    int m = blockIdx.x * 8 + warp;
    const float* r = in + (size_t)m * HIDN;
    float v[8];
    float s = 0.f;
    #pragma unroll
    for (int i = 0; i < 8; i++) { v[i] = r[lane + 32 * i]; s += v[i]; }
    #pragma unroll
    for (int o = 16; o > 0; o >>= 1) s += __shfl_xor_sync(0xffffffffu, s, o);
    float mu = s * (1.0f / HIDN);
    float q = 0.f;
    #pragma unroll
    for (int i = 0; i < 8; i++) { float d = v[i] - mu; q += d * d; }
    #pragma unroll
    for (int o = 16; o > 0; o >>= 1) q += __shfl_xor_sync(0xffffffffu, q, o);
    float inv = rsqrtf(q * (1.0f / HIDN) + LN_EPS);
    #pragma unroll
    for (int i = 0; i < 8; i++) {
        int c = lane + 32 * i;
        float y = (v[i] - mu) * inv * g[c] + b[c];
        if (OUTB) {
            __nv_bfloat16 hh, ll;
            split_bf16(y, hh, ll);
            oh[(size_t)m * HIDN + c] = hh;
            ol[(size_t)m * HIDN + c] = ll;
        } else {
            outF[(size_t)m * HIDN + c] = y;
        }
    }
}

// ======================= K_final =======================
__global__ void k_final(const float* __restrict__ x, const float* __restrict__ ww,
                        const float* __restrict__ bw, float* __restrict__ out) {
    __shared__ float ww_s[NVAR * 257];
    __shared__ float bw_s[NVAR];
    int t = threadIdx.x;
    int warp = t >> 5, lane = t & 31;
    for (int idx = t; idx < HIDN * NVAR; idx += 256) {
        int c = idx / NVAR, j = idx % NVAR;
        ww_s[j * 257 + c] = ww[idx];
    }
    if (t < NVAR) bw_s[t] = bw[t];
    __syncthreads();

    const size_t WOFF = (size_t)MTOK * HIDN;
    #pragma unroll
    for (int tk = 0; tk < 2; tk++) {
        int m = blockIdx.x * 16 + warp * 2 + tk;
        const float* pr = g_proc + (size_t)m * HIDN;
        float lg[NVAR] = {};
        #pragma unroll
        for (int i = 0; i < 8; i++) {
            int c = lane + 32 * i;
            float p = pr[c];
            #pragma unroll
            for (int j = 0; j < NVAR; j++) lg[j] += p * ww_s[j * 257 + c];
        }
        #pragma unroll
        for (int j = 0; j < NVAR; j++) {
            #pragma unroll
            for (int o = 16; o > 0; o >>= 1) lg[j] += __shfl_xor_sync(0xffffffffu, lg[j], o);
            lg[j] += bw_s[j];
        }
        float mx = -1e30f;
        #pragma unroll
        for (int j = 0; j < NVAR; j++) mx = fmaxf(mx, lg[j]);
        float sum = 0.f;
        #pragma unroll
        for (int j = 0; j < NVAR; j++) { lg[j] = __expf(lg[j] - mx); sum += lg[j]; }
        float inv = 1.0f / sum;
        #pragma unroll
        for (int j = 0; j < NVAR; j++) lg[j] *= inv;

        float myw = 0.f;
        #pragma unroll
        for (int j = 0; j < NVAR; j++) if (lane == j) myw = lg[j];
        if (lane < NVAR) out[WOFF + (size_t)m * NVAR + lane] = myw;

        const float* xb = x + (size_t)m * (NVAR * HIDN);
        #pragma unroll
        for (int i = 0; i < 8; i++) {
            int c = lane + 32 * i;
            float a = 0.f;
            #pragma unroll
            for (int v = 0; v < NVAR; v++) a += lg[v] * xb[v * HIDN + c];
            out[(size_t)m * HIDN + c] = a;
        }
    }
}

extern "C" void kernel_launch(void* const* d_in, const int* in_sizes, int n_in,
                              void* d_out, int out_size) {
    (void)in_sizes; (void)n_in; (void)out_size;
    const float* x     = (const float*)d_in[0];
    const float* cls   = (const float*)d_in[1];
    const float* wq    = (const float*)d_in[2];
    const float* bq    = (const float*)d_in[3];
    const float* wk    = (const float*)d_in[4];
    const float* bk    = (const float*)d_in[5];
    const float* wv    = (const float*)d_in[6];
    const float* bv    = (const float*)d_in[7];
    const float* wo    = (const float*)d_in[8];
    const float* bo    = (const float*)d_in[9];
    const float* ln1_g = (const float*)d_in[10];
    const float* ln1_b = (const float*)d_in[11];
    const float* w1    = (const float*)d_in[12];
    const float* b1    = (const float*)d_in[13];
    const float* w2    = (const float*)d_in[14];
    const float* b2    = (const float*)d_in[15];
    const float* ln2_g = (const float*)d_in[16];
    const float* ln2_b = (const float*)d_in[17];
    const float* ww    = (const float*)d_in[18];
    const float* bw    = (const float*)d_in[19];
    float* out = (float*)d_out;

    cudaFuncSetAttribute(k_mma<0>, cudaFuncAttributeMaxDynamicSharedMemorySize, MM_TOTAL);
    cudaFuncSetAttribute(k_mma<1>, cudaFuncAttributeMaxDynamicSharedMemorySize, MM_TOTAL);

    void *p_ctxh, *p_ctxl, *p_ao, *p_h1h, *p_h1l, *p_h2h, *p_h2l, *p_h3, *p_proc, *p_cbias;
    void *p_woh, *p_wol, *p_w1h, *p_w1l, *p_w2h, *p_w2l, *p_wvh, *p_wvl;
    cudaGetSymbolAddress(&p_ctxh, g_ctxh);  cudaGetSymbolAddress(&p_ctxl, g_ctxl);
    cudaGetSymbolAddress(&p_ao, g_ao);      cudaGetSymbolAddress(&p_h1h, g_h1h);
    cudaGetSymbolAddress(&p_h1l, g_h1l);    cudaGetSymbolAddress(&p_h2h, g_h2h);
    cudaGetSymbolAddress(&p_h2l, g_h2l);    cudaGetSymbolAddress(&p_h3, g_h3);
    cudaGetSymbolAddress(&p_proc, g_proc);  cudaGetSymbolAddress(&p_cbias, g_cbias);
    cudaGetSymbolAddress(&p_woh, g_woT_h);  cudaGetSymbolAddress(&p_wol, g_woT_l);
    cudaGetSymbolAddress(&p_w1h, g_w1T_h);  cudaGetSymbolAddress(&p_w1l, g_w1T_l);
    cudaGetSymbolAddress(&p_w2h, g_w2T_h);  cudaGetSymbolAddress(&p_w2l, g_w2T_l);
    cudaGetSymbolAddress(&p_wvh, g_wvT_h);  cudaGetSymbolAddress(&p_wvl, g_wvT_l);

    k_pre<<<1, 256>>>(cls, wq, bq, wk, bk, wo, bo, bv);
    k_wsplit<<<(HIDN * HIDN + 255) / 256, 256>>>(wo, (__nv_bfloat16*)p_woh, (__nv_bfloat16*)p_wol, HIDN, HIDN);
    k_wsplit<<<(HIDN * FFD + 255) / 256, 256>>>(w1, (__nv_bfloat16*)p_w1h, (__nv_bfloat16*)p_w1l, HIDN, FFD);
    k_wsplit<<<(FFD * HIDN + 255) / 256, 256>>>(w2, (__nv_bfloat16*)p_w2h, (__nv_bfloat16*)p_w2l, FFD, HIDN);
    k_wsplit<<<(HIDN * HIDN + 255) / 256, 256>>>(wv, (__nv_bfloat16*)p_wvh, (__nv_bfloat16*)p_wvl, HIDN, HIDN);

    k1_attn<<<MTOK, 256>>>(x);
    k_mma_ctx<<<dim3(MTOK / 128, NHEAD), 256>>>();

    // o-proj: ao = ctx @ woT^T + cbias   (K=256, N=256)
    k_mma<0><<<dim3(HIDN / 128, MTOK / 128), 256, MM_TOTAL>>>(
        (const __nv_bfloat16*)p_ctxh, (const __nv_bfloat16*)p_ctxl,
        (const __nv_bfloat16*)p_woh, (const __nv_bfloat16*)p_wol,
        (const float*)p_cbias, (float*)p_ao, nullptr, nullptr, HIDN, HIDN);

    k_ln<1><<<MTOK / 8, 256>>>((const float*)p_ao, ln1_g, ln1_b, nullptr,
                               (__nv_bfloat16*)p_h1h, (__nv_bfloat16*)p_h1l);

    // FF1: h2 = gelu(h1 @ w1 + b1)    (K=256, N=1024)
    k_mma<1><<<dim3(FFD / 128, MTOK / 128), 256, MM_TOTAL>>>(
        (const __nv_bfloat16*)p_h1h, (const __nv_bfloat16*)p_h1l,
        (const __nv_bfloat16*)p_w1h, (const __nv_bfloat16*)p_w1l,
        b1, nullptr, (__nv_bfloat16*)p_h2h, (__nv_bfloat16*)p_h2l, HIDN, FFD);

    // FF2: h3 = h2 @ w2 + b2          (K=1024, N=256)
    k_mma<0><<<dim3(HIDN / 128, MTOK / 128), 256, MM_TOTAL>>>(
        (const __nv_bfloat16*)p_h2h, (const __nv_bfloat16*)p_h2l,
        (const __nv_bfloat16*)p_w2h, (const __nv_bfloat16*)p_w2l,
        b2, (float*)p_h3, nullptr, nullptr, FFD, HIDN);

    k_ln<0><<<MTOK / 8, 256>>>((const float*)p_h3, ln2_g, ln2_b, (float*)p_proc, nullptr, nullptr);

    k_final<<<MTOK / 16, 256>>>(x, ww, bw, out);
}

// round 5
// speedup vs baseline: 1.7420x; 1.2095x over previous
#include <cuda_runtime.h>
#include <cuda_bf16.h>
#include <math.h>
#include <cstdint>

#define HIDN 256
#define NVAR 20
#define NHEAD 8
#define DHEAD 32
#define MTOK 16384          // B*T
#define FFD 1024
#define ATT_SCALE 0.17677669529663687f
#define LN_EPS 1e-5f

// ======================= helpers =======================
__device__ __forceinline__ uint32_t smem_to_u32(const void* p) {
    uint32_t a;
    asm("{ .reg .u64 t; cvta.to.shared.u64 t, %1; cvt.u32.u64 %0, t; }" : "=r"(a) : "l"(p));
    return a;
}
__device__ __forceinline__ void ldm_x4(uint32_t& r0, uint32_t& r1, uint32_t& r2, uint32_t& r3,
                                       uint32_t addr) {
    asm volatile("ldmatrix.sync.aligned.m8n8.x4.shared.b16 {%0,%1,%2,%3}, [%4];"
                 : "=r"(r0), "=r"(r1), "=r"(r2), "=r"(r3) : "r"(addr));
}
__device__ __forceinline__ void mma_bf16(float* c, const uint32_t* a, const uint32_t* b) {
    asm volatile(
        "mma.sync.aligned.m16n8k16.row.col.f32.bf16.bf16.f32 "
        "{%0,%1,%2,%3}, {%4,%5,%6,%7}, {%8,%9}, {%0,%1,%2,%3};"
        : "+f"(c[0]), "+f"(c[1]), "+f"(c[2]), "+f"(c[3])
        : "r"(a[0]), "r"(a[1]), "r"(a[2]), "r"(a[3]), "r"(b[0]), "r"(b[1]));
}
__device__ __forceinline__ void cp16(uint32_t dst, const void* src) {
    asm volatile("cp.async.cg.shared.global [%0], [%1], 16;" :: "r"(dst), "l"(src));
}
#define CP_COMMIT() asm volatile("cp.async.commit_group;" ::: "memory")
#define CP_WAIT0()  asm volatile("cp.async.wait_group 0;" ::: "memory")
__device__ __forceinline__ void split_bf16(float v, __nv_bfloat16& h, __nv_bfloat16& l) {
    h = __float2bfloat16(v);
    l = __float2bfloat16(v - __bfloat162float(h));
}
__device__ __forceinline__ float gelu_exact(float v) {
    return 0.5f * v * (1.0f + erff(v * 0.70710678118654752f));
}

// ======================= scratch =======================
__device__ __align__(256) float g_S[NHEAD * HIDN];
__device__ __align__(256) float g_sbias[NHEAD];
__device__ __align__(256) float g_cbias[HIDN];
__device__ __align__(256) __nv_bfloat16 g_xwh[(size_t)MTOK * 2048];
__device__ __align__(256) __nv_bfloat16 g_xwl[(size_t)MTOK * 2048];
__device__ __align__(256) __nv_bfloat16 g_ctxh[(size_t)MTOK * HIDN];
__device__ __align__(256) __nv_bfloat16 g_ctxl[(size_t)MTOK * HIDN];
__device__ __align__(256) float g_ao[(size_t)MTOK * HIDN];
__device__ __align__(256) __nv_bfloat16 g_h1h[(size_t)MTOK * HIDN];
__device__ __align__(256) __nv_bfloat16 g_h1l[(size_t)MTOK * HIDN];
__device__ __align__(256) __nv_bfloat16 g_h2h[(size_t)MTOK * FFD];
__device__ __align__(256) __nv_bfloat16 g_h2l[(size_t)MTOK * FFD];
__device__ __align__(256) float g_h3[(size_t)MTOK * HIDN];
__device__ __align__(256) float g_proc[(size_t)MTOK * HIDN];
__device__ __align__(256) __nv_bfloat16 g_woT_h[HIDN * HIDN], g_woT_l[HIDN * HIDN];
__device__ __align__(256) __nv_bfloat16 g_w1T_h[FFD * HIDN],  g_w1T_l[FFD * HIDN];
__device__ __align__(256) __nv_bfloat16 g_w2T_h[HIDN * FFD],  g_w2T_l[HIDN * FFD];
__device__ __align__(256) __nv_bfloat16 g_wvT_h[HIDN * HIDN], g_wvT_l[HIDN * HIDN];

// ======================= K0: tiny precompute =======================
__global__ void k_pre(const float* __restrict__ cls, const float* __restrict__ wq,
                      const float* __restrict__ bq, const float* __restrict__ wk,
                      const float* __restrict__ bk, const float* __restrict__ wo,
                      const float* __restrict__ bo, const float* __restrict__ bv) {
    __shared__ float q_s[HIDN];
    int t = threadIdx.x;
    float acc = bq[t];
    for (int c = 0; c < HIDN; c++) acc += cls[c] * wq[c * HIDN + t];
    q_s[t] = acc;
    __syncthreads();
    for (int idx = t; idx < NHEAD * HIDN; idx += 256) {
        int h = idx >> 8, c = idx & 255;
        float s = 0.f;
        #pragma unroll 8
        for (int d = 0; d < DHEAD; d++) s += wk[c * HIDN + h * DHEAD + d] * q_s[h * DHEAD + d];
        g_S[idx] = s;
    }
    if (t < NHEAD) {
        float s = 0.f;
        for (int d = 0; d < DHEAD; d++) s += bk[t * DHEAD + d] * q_s[t * DHEAD + d];
        g_sbias[t] = s;
    }
    float cb = bo[t];
    for (int c = 0; c < HIDN; c++) cb += bv[c] * wo[c * HIDN + t];
    g_cbias[t] = cb;
}

// ======================= merged weight transpose+split =======================
__global__ void k_wsplit_all(const float* __restrict__ wo, const float* __restrict__ w1,
                             const float* __restrict__ w2, const float* __restrict__ wv) {
    int which = blockIdx.y;
    const float* w;
    __nv_bfloat16 *hi, *lo;
    int K, N;
    if (which == 0)      { w = wo; hi = g_woT_h; lo = g_woT_l; K = HIDN; N = HIDN; }
    else if (which == 1) { w = w1; hi = g_w1T_h; lo = g_w1T_l; K = HIDN; N = FFD; }
    else if (which == 2) { w = w2; hi = g_w2T_h; lo = g_w2T_l; K = FFD;  N = HIDN; }
    else                 { w = wv; hi = g_wvT_h; lo = g_wvT_l; K = HIDN; N = HIDN; }
    int total = K * N;
    for (int idx = blockIdx.x * 256 + threadIdx.x; idx < total; idx += gridDim.x * 256) {
        int k = idx / N, n = idx % N;
        __nv_bfloat16 h, l;
        split_bf16(w[idx], h, l);
        hi[(size_t)n * K + k] = h;
        lo[(size_t)n * K + k] = l;
    }
}

// ======================= K1: fused attention -> xw hi/lo =======================
// x read into smem ONCE; each warp keeps all 8 heads' S-slices in registers and
// handles variables v = warp, warp+8, warp+16 -> smem crossbar traffic 8x lower.
#define XROW 260
__global__ void __launch_bounds__(256) k1_attn(const float* __restrict__ x) {
    __shared__ float x_s[NVAR * XROW];
    __shared__ float sc_s[NHEAD * NVAR];    // [h][v]
    __shared__ float attn_s[NVAR * NHEAD];  // [v][h]
    int m = blockIdx.x;
    int t = threadIdx.x, lane = t & 31, w = t >> 5;
    const float* xb = x + (size_t)m * (NVAR * HIDN);

    // fill x_s (float4 both sides)
    #pragma unroll
    for (int i = 0; i < 5; i++) {
        int e4 = t + i * 256;
        float4 val = *(const float4*)(xb + e4 * 4);
        int e = e4 * 4;
        int v = e >> 8, c = e & 255;
        *(float4*)&x_s[v * XROW + c] = val;
    }

    // S slices: s_r[h][i], channel c = lane*8 + i
    float s_r[8][8];
    #pragma unroll
    for (int hh = 0; hh < 8; hh++) {
        float4 s0 = *(const float4*)&g_S[hh * 256 + lane * 8];
        float4 s1 = *(const float4*)&g_S[hh * 256 + lane * 8 + 4];
        s_r[hh][0] = s0.x; s_r[hh][1] = s0.y; s_r[hh][2] = s0.z; s_r[hh][3] = s0.w;
        s_r[hh][4] = s1.x; s_r[hh][5] = s1.y; s_r[hh][6] = s1.z; s_r[hh][7] = s1.w;
    }
    __syncthreads();

    // scores: warp w handles v = w, w+8, w+16 for ALL heads
    for (int v = w; v < NVAR; v += 8) {
        float4 xa = *(const float4*)&x_s[v * XROW + lane * 8];
        float4 xc = *(const float4*)&x_s[v * XROW + lane * 8 + 4];
        float xr[8] = {xa.x, xa.y, xa.z, xa.w, xc.x, xc.y, xc.z, xc.w};
        float sums[8];
        #pragma unroll
        for (int hh = 0; hh < 8; hh++) {
            float s = 0.f;
            #pragma unroll
            for (int i = 0; i < 8; i++) s += xr[i] * s_r[hh][i];
            sums[hh] = s;
        }
        #pragma unroll
        for (int hh = 0; hh < 8; hh++) {
            #pragma unroll
            for (int o = 16; o > 0; o >>= 1)
                sums[hh] += __shfl_xor_sync(0xffffffffu, sums[hh], o);
        }
        if (lane == 0) {
            #pragma unroll
            for (int hh = 0; hh < 8; hh++)
                sc_s[hh * NVAR + v] = (sums[hh] + g_sbias[hh]) * ATT_SCALE;
        }
    }
    __syncthreads();

    // softmax: warp w == head w, lanes = variables
    {
        float my = (lane < NVAR) ? sc_s[w * NVAR + lane] : -1e30f;
        float mx = my;
        #pragma unroll
        for (int o = 16; o > 0; o >>= 1) mx = fmaxf(mx, __shfl_xor_sync(0xffffffffu, mx, o));
        float e = (lane < NVAR) ? __expf(my - mx) : 0.f;
        float s = e;
        #pragma unroll
        for (int o = 16; o > 0; o >>= 1) s += __shfl_xor_sync(0xffffffffu, s, o);
        if (lane < NVAR) attn_s[lane * 8 + w] = e / s;
    }
    __syncthreads();

    // xw: thread t = channel
    float acc[NHEAD] = {};
    #pragma unroll 4
    for (int v = 0; v < NVAR; v++) {
        float xv = x_s[v * XROW + t];
        float4 a0 = *(const float4*)&attn_s[v * 8];
        float4 a1 = *(const float4*)&attn_s[v * 8 + 4];
        acc[0] += a0.x * xv; acc[1] += a0.y * xv; acc[2] += a0.z * xv; acc[3] += a0.w * xv;
        acc[4] += a1.x * xv; acc[5] += a1.y * xv; acc[6] += a1.z * xv; acc[7] += a1.w * xv;
    }
    size_t base = (size_t)m * 2048;
    #pragma unroll
    for (int j = 0; j < NHEAD; j++) {
        __nv_bfloat16 hh, ll;
        split_bf16(acc[j], hh, ll);
        g_xwh[base + j * 256 + t] = hh;
        g_xwl[base + j * 256 + t] = ll;
    }
}

// ======================= main split-bf16 MMA GEMM (cp.async 2-stage) ===============
// C[M,N] = A[M,K] @ B[N,K]^T; tile 128x128, KC=32, 8 warps (4m x 2n), warp tile 32x64
// stage layout (stride 80B rows, conflict-free + 16B aligned):
#define KC2 32
#define RS2 80
#define STG_SZ 40960          // 4 arrays * 128 rows * 80B
#define MM_TOTAL2 (2 * STG_SZ)

template <int MODE>
__global__ void __launch_bounds__(256, 2) k_mma(
    const __nv_bfloat16* __restrict__ Ah, const __nv_bfloat16* __restrict__ Al,
    const __nv_bfloat16* __restrict__ Bh, const __nv_bfloat16* __restrict__ Bl,
    const float* __restrict__ bias, float* __restrict__ outF,
    __nv_bfloat16* __restrict__ outH, __nv_bfloat16* __restrict__ outL,
    int K, int N) {
    extern __shared__ __align__(16) char smem[];
    uint32_t sb = smem_to_u32(smem);
    int t = threadIdx.x, lane = t & 31, wid = t >> 5;
    int wm = wid & 3, wn = wid >> 2;
    int row0 = blockIdx.y * 128, col0 = blockIdx.x * 128;

    float acc[2][8][4] = {};
    const int nch = K / KC2;

    // stage loader: 4 arrays x 128 rows x 2... (32 cols bf16 = 64B = 4 x 16B segs)
    auto load_stage = [&](int ch, int s) {
        int kk = ch * KC2;
        uint32_t sbase = sb + s * STG_SZ;
        #pragma unroll
        for (int i = 0; i < 8; i++) {
            int idx = t + i * 256;
            int arr = idx >> 9;
            int rem = idx & 511;
            int row = rem >> 2, seg = rem & 3;
            const __nv_bfloat16* src = (arr == 0) ? Ah : (arr == 1) ? Al : (arr == 2) ? Bh : Bl;
            size_t g = (size_t)(((arr < 2) ? row0 : col0) + row) * K + kk + seg * 8;
            cp16(sbase + arr * 10240 + row * RS2 + seg * 16, src + g);
        }
    };

    load_stage(0, 0);
    CP_COMMIT();

    for (int ch = 0; ch < nch; ch++) {
        CP_WAIT0();
        __syncthreads();
        if (ch + 1 < nch) { load_stage(ch + 1, (ch + 1) & 1); CP_COMMIT(); }

        uint32_t st = sb + (ch & 1) * STG_SZ;
        #pragma unroll
        for (int ks = 0; ks < 2; ks++) {
            uint32_t a_h[2][4], a_l[2][4];
            #pragma unroll
            for (int mt = 0; mt < 2; mt++) {
                uint32_t off = (uint32_t)((wm * 32 + mt * 16 + (lane & 15)) * RS2
                                          + (ks * 16 + ((lane >> 4) << 3)) * 2);
                ldm_x4(a_h[mt][0], a_h[mt][1], a_h[mt][2], a_h[mt][3], st + off);
                ldm_x4(a_l[mt][0], a_l[mt][1], a_l[mt][2], a_l[mt][3], st + 10240 + off);
            }
            #pragma unroll
            for (int ng = 0; ng < 4; ng++) {
                uint32_t b_h[2][2], b_l[2][2];
                uint32_t off = (uint32_t)((wn * 64 + ng * 16 + ((lane & 16) >> 1) + (lane & 7)) * RS2
                                          + (ks * 16 + (lane & 8)) * 2);
                ldm_x4(b_h[0][0], b_h[0][1], b_h[1][0], b_h[1][1], st + 20480 + off);
                ldm_x4(b_l[0][0], b_l[0][1], b_l[1][0], b_l[1][1], st + 30720 + off);
                #pragma unroll
                for (int mt = 0; mt < 2; mt++) {
                    #pragma unroll
                    for (int sub = 0; sub < 2; sub++) {
                        float* a = acc[mt][ng * 2 + sub];
                        mma_bf16(a, a_h[mt], b_h[sub]);
                        mma_bf16(a, a_h[mt], b_l[sub]);
                        mma_bf16(a, a_l[mt], b_h[sub]);
                    }
                }
            }
        }
        __syncthreads();
    }

    // ---- epilogue ----
    int g = lane >> 2, q = lane & 3;
    #pragma unroll
    for (int mt = 0; mt < 2; mt++) {
        int m0 = row0 + wm * 32 + mt * 16 + g;
        #pragma unroll
        for (int nt = 0; nt < 8; nt++) {
            int n = col0 + wn * 64 + nt * 8 + q * 2;
            float b0 = bias[n], b1 = bias[n + 1];
            float v00 = acc[mt][nt][0] + b0, v01 = acc[mt][nt][1] + b1;
            float v10 = acc[mt][nt][2] + b0, v11 = acc[mt][nt][3] + b1;
            if (MODE == 1) {
                v00 = gelu_exact(v00); v01 = gelu_exact(v01);
                v10 = gelu_exact(v10); v11 = gelu_exact(v11);
                __nv_bfloat16 h0, l0, h1, l1;
                split_bf16(v00, h0, l0); split_bf16(v01, h1, l1);
                *(__nv_bfloat162*)(outH + (size_t)m0 * N + n) = __nv_bfloat162(h0, h1);
                *(__nv_bfloat162*)(outL + (size_t)m0 * N + n) = __nv_bfloat162(l0, l1);
                split_bf16(v10, h0, l0); split_bf16(v11, h1, l1);
                *(__nv_bfloat162*)(outH + (size_t)(m0 + 8) * N + n) = __nv_bfloat162(h0, h1);
                *(__nv_bfloat162*)(outL + (size_t)(m0 + 8) * N + n) = __nv_bfloat162(l0, l1);
            } else {
                *(float2*)(outF + (size_t)m0 * N + n) = make_float2(v00, v01);
                *(float2*)(outF + (size_t)(m0 + 8) * N + n) = make_float2(v10, v11);
            }
        }
    }
}

// ======================= per-head ctx MMA GEMM (as R4) =======================
#define KC 64
#define A_RS 144
#define CT_AH 0
#define CT_AL 18432
#define CT_BH 36864
#define CT_BL 41472
__global__ void __launch_bounds__(256) k_mma_ctx() {
    __shared__ __align__(16) char smem[46080];
    uint32_t sb = smem_to_u32(smem);
    int t = threadIdx.x, lane = t & 31, wid = t >> 5;
    int row0 = blockIdx.x * 128, h = blockIdx.y;

    float acc[4][4] = {};

    for (int kk = 0; kk < HIDN; kk += KC) {
        #pragma unroll
        for (int i = 0; i < 8; i++) {
            int idx = t + i * 256;
            int arr = idx >> 10;
            int rem = idx & 1023;
            int row = rem >> 3, seg = rem & 7;
            const __nv_bfloat16* src = arr ? g_xwl : g_xwh;
            size_t gidx = (size_t)(row0 + row) * 2048 + h * 256 + kk + seg * 8;
            *(uint4*)(smem + arr * 18432 + row * A_RS + seg * 16) = *(const uint4*)(src + gidx);
        }
        #pragma unroll
        for (int i = 0; i < 2; i++) {
            int idx = t + i * 256;
            int arr = idx >> 8;
            int rem = idx & 255;
            int row = rem >> 3, seg = rem & 7;
            const __nv_bfloat16* src = arr ? g_wvT_l : g_wvT_h;
            size_t gidx = (size_t)(h * 32 + row) * HIDN + kk + seg * 8;
            *(uint4*)(smem + CT_BH + arr * 4608 + row * A_RS + seg * 16) = *(const uint4*)(src + gidx);
        }
        __syncthreads();

        #pragma unroll
        for (int ks = 0; ks < 4; ks++) {
            uint32_t a_h[4], a_l[4], b_h[4][2], b_l[4][2];
            uint32_t aoff = (uint32_t)((wid * 16 + (lane & 15)) * A_RS
                                       + (ks * 16 + ((lane >> 4) << 3)) * 2);
            ldm_x4(a_h[0], a_h[1], a_h[2], a_h[3], sb + CT_AH + aoff);
            ldm_x4(a_l[0], a_l[1], a_l[2], a_l[3], sb + CT_AL + aoff);
            #pragma unroll
            for (int ng = 0; ng < 2; ng++) {
                uint32_t boff = (uint32_t)((ng * 16 + ((lane & 16) >> 1) + (lane & 7)) * A_RS
                                           + (ks * 16 + (lane & 8)) * 2);
                ldm_x4(b_h[2 * ng][0], b_h[2 * ng][1], b_h[2 * ng + 1][0], b_h[2 * ng + 1][1],
                       sb + CT_BH + boff);
                ldm_x4(b_l[2 * ng][0], b_l[2 * ng][1], b_l[2 * ng + 1][0], b_l[2 * ng + 1][1],
                       sb + CT_BL + boff);
            }
            #pragma unroll
            for (int nt = 0; nt < 4; nt++) {
                mma_bf16(acc[nt], a_h, b_h[nt]);
                mma_bf16(acc[nt], a_h, b_l[nt]);
                mma_bf16(acc[nt], a_l, b_h[nt]);
            }
        }
        __syncthreads();
    }

    int g = lane >> 2, q = lane & 3;
    int m0 = row0 + wid * 16 + g;
    #pragma unroll
    for (int nt = 0; nt < 4; nt++) {
        int n = h * 32 + nt * 8 + q * 2;
        __nv_bfloat16 h0, l0, h1, l1;
        split_bf16(acc[nt][0], h0, l0); split_bf16(acc[nt][1], h1, l1);
        *(__nv_bfloat162*)(g_ctxh + (size_t)m0 * HIDN + n) = __nv_bfloat162(h0, h1);
        *(__nv_bfloat162*)(g_ctxl + (size_t)m0 * HIDN + n) = __nv_bfloat162(l0, l1);
        split_bf16(acc[nt][2], h0, l0); split_bf16(acc[nt][3], h1, l1);
        *(__nv_bfloat162*)(g_ctxh + (size_t)(m0 + 8) * HIDN + n) = __nv_bfloat162(h0, h1);
        *(__nv_bfloat162*)(g_ctxl + (size_t)(m0 + 8) * HIDN + n) = __nv_bfloat162(l0, l1);
    }
}

// ======================= LayerNorm =======================
template <int OUTB>
__global__ void k_ln(const float* __restrict__ in, const float* __restrict__ g,
                     const float* __restrict__ b, float* __restrict__ outF,
                     __nv_bfloat16* __restrict__ oh, __nv_bfloat16* __restrict__ ol) {
    int warp = threadIdx.x >> 5, lane = threadIdx.x & 31;
    int m = blockIdx.x * 8 + warp;
    const float* r = in + (size_t)m * HIDN;
    float v[8];
    float s = 0.f;
    #pragma unroll
    for (int i = 0; i < 8; i++) { v[i] = r[lane + 32 * i]; s += v[i]; }
    #pragma unroll
    for (int o = 16; o > 0; o >>= 1) s += __shfl_xor_sync(0xffffffffu, s, o);
    float mu = s * (1.0f / HIDN);
    float q = 0.f;
    #pragma unroll
    for (int i = 0; i < 8; i++) { float d = v[i] - mu; q += d * d; }
    #pragma unroll
    for (int o = 16; o > 0; o >>= 1) q += __shfl_xor_sync(0xffffffffu, q, o);
    float inv = rsqrtf(q * (1.0f / HIDN) + LN_EPS);
    #pragma unroll
    for (int i = 0; i < 8; i++) {
        int c = lane + 32 * i;
        float y = (v[i] - mu) * inv * g[c] + b[c];
        if (OUTB) {
            __nv_bfloat16 hh, ll;
            split_bf16(y, hh, ll);
            oh[(size_t)m * HIDN + c] = hh;
            ol[(size_t)m * HIDN + c] = ll;
        } else {
            outF[(size_t)m * HIDN + c] = y;
        }
    }
}

// ======================= K_final =======================
__global__ void k_final(const float* __restrict__ x, const float* __restrict__ ww,
                        const float* __restrict__ bw, float* __restrict__ out) {
    __shared__ float ww_s[NVAR * 257];
    __shared__ float bw_s[NVAR];
    int t = threadIdx.x;
    int warp = t >> 5, lane = t & 31;
    for (int idx = t; idx < HIDN * NVAR; idx += 256) {
        int c = idx / NVAR, j = idx % NVAR;
        ww_s[j * 257 + c] = ww[idx];
    }
    if (t < NVAR) bw_s[t] = bw[t];
    __syncthreads();

    const size_t WOFF = (size_t)MTOK * HIDN;
    #pragma unroll
    for (int tk = 0; tk < 2; tk++) {
        int m = blockIdx.x * 16 + warp * 2 + tk;
        const float* pr = g_proc + (size_t)m * HIDN;
        float lg[NVAR] = {};
        #pragma unroll
        for (int i = 0; i < 8; i++) {
            int c = lane + 32 * i;
            float p = pr[c];
            #pragma unroll
            for (int j = 0; j < NVAR; j++) lg[j] += p * ww_s[j * 257 + c];
        }
        #pragma unroll
        for (int j = 0; j < NVAR; j++) {
            #pragma unroll
            for (int o = 16; o > 0; o >>= 1) lg[j] += __shfl_xor_sync(0xffffffffu, lg[j], o);
            lg[j] += bw_s[j];
        }
        float mx = -1e30f;
        #pragma unroll
        for (int j = 0; j < NVAR; j++) mx = fmaxf(mx, lg[j]);
        float sum = 0.f;
        #pragma unroll
        for (int j = 0; j < NVAR; j++) { lg[j] = __expf(lg[j] - mx); sum += lg[j]; }
        float inv = 1.0f / sum;
        #pragma unroll
        for (int j = 0; j < NVAR; j++) lg[j] *= inv;

        float myw = 0.f;
        #pragma unroll
        for (int j = 0; j < NVAR; j++) if (lane == j) myw = lg[j];
        if (lane < NVAR) out[WOFF + (size_t)m * NVAR + lane] = myw;

        const float* xb = x + (size_t)m * (NVAR * HIDN);
        #pragma unroll
        for (int i = 0; i < 8; i++) {
            int c = lane + 32 * i;
            float a = 0.f;
            #pragma unroll
            for (int v = 0; v < NVAR; v++) a += lg[v] * xb[v * HIDN + c];
            out[(size_t)m * HIDN + c] = a;
        }
    }
}

extern "C" void kernel_launch(void* const* d_in, const int* in_sizes, int n_in,
                              void* d_out, int out_size) {
    (void)in_sizes; (void)n_in; (void)out_size;
    const float* x     = (const float*)d_in[0];
    const float* cls   = (const float*)d_in[1];
    const float* wq    = (const float*)d_in[2];
    const float* bq    = (const float*)d_in[3];
    const float* wk    = (const float*)d_in[4];
    const float* bk    = (const float*)d_in[5];
    const float* wv    = (const float*)d_in[6];
    const float* bv    = (const float*)d_in[7];
    const float* wo    = (const float*)d_in[8];
    const float* bo    = (const float*)d_in[9];
    const float* ln1_g = (const float*)d_in[10];
    const float* ln1_b = (const float*)d_in[11];
    const float* w1    = (const float*)d_in[12];
    const float* b1    = (const float*)d_in[13];
    const float* w2    = (const float*)d_in[14];
    const float* b2    = (const float*)d_in[15];
    const float* ln2_g = (const float*)d_in[16];
    const float* ln2_b = (const float*)d_in[17];
    const float* ww    = (const float*)d_in[18];
    const float* bw    = (const float*)d_in[19];
    float* out = (float*)d_out;

    cudaFuncSetAttribute(k_mma<0>, cudaFuncAttributeMaxDynamicSharedMemorySize, MM_TOTAL2);
    cudaFuncSetAttribute(k_mma<1>, cudaFuncAttributeMaxDynamicSharedMemorySize, MM_TOTAL2);

    void *p_ctxh, *p_ctxl, *p_ao, *p_h1h, *p_h1l, *p_h2h, *p_h2l, *p_h3, *p_proc, *p_cbias;
    void *p_woh, *p_wol, *p_w1h, *p_w1l, *p_w2h, *p_w2l;
    cudaGetSymbolAddress(&p_ctxh, g_ctxh);  cudaGetSymbolAddress(&p_ctxl, g_ctxl);
    cudaGetSymbolAddress(&p_ao, g_ao);      cudaGetSymbolAddress(&p_h1h, g_h1h);
    cudaGetSymbolAddress(&p_h1l, g_h1l);    cudaGetSymbolAddress(&p_h2h, g_h2h);
    cudaGetSymbolAddress(&p_h2l, g_h2l);    cudaGetSymbolAddress(&p_h3, g_h3);
    cudaGetSymbolAddress(&p_proc, g_proc);  cudaGetSymbolAddress(&p_cbias, g_cbias);
    cudaGetSymbolAddress(&p_woh, g_woT_h);  cudaGetSymbolAddress(&p_wol, g_woT_l);
    cudaGetSymbolAddress(&p_w1h, g_w1T_h);  cudaGetSymbolAddress(&p_w1l, g_w1T_l);
    cudaGetSymbolAddress(&p_w2h, g_w2T_h);  cudaGetSymbolAddress(&p_w2l, g_w2T_l);

    k_pre<<<1, 256>>>(cls, wq, bq, wk, bk, wo, bo, bv);
    k_wsplit_all<<<dim3(256, 4), 256>>>(wo, w1, w2, wv);

    k1_attn<<<MTOK, 256>>>(x);
    k_mma_ctx<<<dim3(MTOK / 128, NHEAD), 256>>>();

    // o-proj: ao = ctx @ woT^T + cbias   (K=256, N=256)
    k_mma<0><<<dim3(HIDN / 128, MTOK / 128), 256, MM_TOTAL2>>>(
        (const __nv_bfloat16*)p_ctxh, (const __nv_bfloat16*)p_ctxl,
        (const __nv_bfloat16*)p_woh, (const __nv_bfloat16*)p_wol,
        (const float*)p_cbias, (float*)p_ao, nullptr, nullptr, HIDN, HIDN);

    k_ln<1><<<MTOK / 8, 256>>>((const float*)p_ao, ln1_g, ln1_b, nullptr,
                               (__nv_bfloat16*)p_h1h, (__nv_bfloat16*)p_h1l);

    // FF1: h2 = gelu(h1 @ w1 + b1)    (K=256, N=1024)
    k_mma<1><<<dim3(FFD / 128, MTOK / 128), 256, MM_TOTAL2>>>(
        (const __nv_bfloat16*)p_h1h, (const __nv_bfloat16*)p_h1l,
        (const __nv_bfloat16*)p_w1h, (const __nv_bfloat16*)p_w1l,
        b1, nullptr, (__nv_bfloat16*)p_h2h, (__nv_bfloat16*)p_h2l, HIDN, FFD);

    // FF2: h3 = h2 @ w2 + b2          (K=1024, N=256)
    k_mma<0><<<dim3(HIDN / 128, MTOK / 128), 256, MM_TOTAL2>>>(
        (const __nv_bfloat16*)p_h2h, (const __nv_bfloat16*)p_h2l,
        (const __nv_bfloat16*)p_w2h, (const __nv_bfloat16*)p_w2l,
        b2, (float*)p_h3, nullptr, nullptr, FFD, HIDN);

    k_ln<0><<<MTOK / 8, 256>>>((const float*)p_h3, ln2_g, ln2_b, (float*)p_proc, nullptr, nullptr);

    k_final<<<MTOK / 16, 256>>>(x, ww, bw, out);
}